// round 11
// baseline (speedup 1.0000x reference)
#include <cuda_runtime.h>
#include <cuda_fp16.h>
#include <cstdint>

#define IN_DIM   16
#define WIDTH    50
#define OUT_DIM  4
#define NL       15            // layer0 (16->50) + 14 hidden (50->50)
#define THREADS  384
#define WARPS    (THREADS/32)

// Weights in smem: per layer, wh+wl fp16 parts, each [56 rows][64 k],
// row stride 128B, 16B-chunk swizzled by (row&7).
// wh part chunk 6 (cols 48-55) holds the MERGED TAIL: [wh48 wh49 wl48 wl49 0 0 0 0]
#define SZ_PART   7168                    // 56*128
#define SZ_LAYER  (2*SZ_PART)             // 14336
#define OFF_WH    0                       // [15][2][56][64]
#define OFF_WO    (NL*SZ_LAYER)           // 215040: [2][8 rows][64]
#define OFF_BIAS  (OFF_WO + 2*1024)       // 217088: [15][56] f32
#define OFF_BO    (OFF_BIAS + NL*56*4)    // 220448: [8] f32
#define SMEM_BYTES (OFF_BO + 32)          // 220480

__device__ __forceinline__ uint32_t smem_u32(const void* p) {
    uint32_t a;
    asm("{ .reg .u64 t; cvta.to.shared.u64 t, %1; cvt.u32.u64 %0, t; }" : "=r"(a) : "l"(p));
    return a;
}
__device__ __forceinline__ void ldsm4(uint32_t* r, uint32_t a) {
    asm volatile("ldmatrix.sync.aligned.m8n8.x4.shared.b16 {%0,%1,%2,%3}, [%4];"
                 : "=r"(r[0]), "=r"(r[1]), "=r"(r[2]), "=r"(r[3]) : "r"(a));
}
__device__ __forceinline__ void ldsm2(uint32_t* r, uint32_t a) {
    asm volatile("ldmatrix.sync.aligned.m8n8.x2.shared.b16 {%0,%1}, [%2];"
                 : "=r"(r[0]), "=r"(r[1]) : "r"(a));
}
__device__ __forceinline__ void ldsm1(uint32_t& r, uint32_t a) {
    asm volatile("ldmatrix.sync.aligned.m8n8.x1.shared.b16 {%0}, [%1];"
                 : "=r"(r) : "r"(a));
}
__device__ __forceinline__ void mma_f16(float* c, const uint32_t* a, uint32_t b0, uint32_t b1) {
    asm("mma.sync.aligned.m16n8k16.row.col.f32.f16.f16.f32 "
        "{%0,%1,%2,%3}, {%4,%5,%6,%7}, {%8,%9}, {%0,%1,%2,%3};"
        : "+f"(c[0]), "+f"(c[1]), "+f"(c[2]), "+f"(c[3])
        : "r"(a[0]), "r"(a[1]), "r"(a[2]), "r"(a[3]), "r"(b0), "r"(b1));
}
__device__ __forceinline__ void mma_f16_8(float* c, uint32_t a0, uint32_t a1, uint32_t b0) {
    asm("mma.sync.aligned.m16n8k8.row.col.f32.f16.f16.f32 "
        "{%0,%1,%2,%3}, {%4,%5}, {%6}, {%0,%1,%2,%3};"
        : "+f"(c[0]), "+f"(c[1]), "+f"(c[2]), "+f"(c[3])
        : "r"(a0), "r"(a1), "r"(b0));
}
// pack two fp32 into one half2 register (RN)
__device__ __forceinline__ uint32_t pack_h2(float a, float b) {
    __half2 t = __float22half2_rn(make_float2(a, b));
    return *reinterpret_cast<uint32_t*>(&t);
}

// swizzled byte offset within one weight part for (row n, col k)
__device__ __host__ __forceinline__ uint32_t swoff(int n, int k) {
    return (uint32_t)(n * 128 + (((k >> 3) << 4) ^ ((n & 7) << 4)) + ((k & 7) << 1));
}

// Build the merged-tail A fragment: k-cols [x48x49 | x48x49 | 0 | 0] from
// quad-lane-0's C[6] halves. 2 shuffles + selects.
__device__ __forceinline__ void make_tail(const uint32_t Ah3[2], int lane,
                                          uint32_t& a0, uint32_t& a1) {
    const int src = lane & 28;
    uint32_t v0 = __shfl_sync(0xFFFFFFFFu, Ah3[0], src);
    uint32_t v1 = __shfl_sync(0xFFFFFFFFu, Ah3[1], src);
    const int t = lane & 3;
    a0 = (t < 2) ? v0 : 0u;
    a1 = (t < 2) ? v1 : 0u;
}

// Dual-tile MMA layer: C[2][7][4] += A[tile] * (wh+wl)^T; B fragments shared,
// A fragment reused across wh and wl parts (activation NOT split).
template <int NK16, bool TAIL>
__device__ __forceinline__ void layer_mma2(const char* sm, uint32_t sb, int layer,
                                           const uint32_t Ah[2][3][4],
                                           const uint32_t at0[2], const uint32_t at1[2],
                                           float C[2][7][4], int lane) {
    const int t2 = (lane & 3) * 2;
    const int ln = lane & 7;
    const int u  = lane >> 3;
    const int nb = ((u >> 1) << 3) + ln;          // row-within-pair (x4 pattern)

    // bias init, shared between the two tiles
    const float* bias = (const float*)(sm + OFF_BIAS + layer * 224);
#pragma unroll
    for (int nt = 0; nt < 7; nt++) {
        float2 bv = *(const float2*)(bias + nt * 8 + t2);
#pragma unroll
        for (int tt = 0; tt < 2; tt++) {
            C[tt][nt][0] = bv.x; C[tt][nt][1] = bv.y;
            C[tt][nt][2] = bv.x; C[tt][nt][3] = bv.y;
        }
    }

    const uint32_t hibase = sb + OFF_WH + (uint32_t)layer * SZ_LAYER;
    const uint32_t lobase = hibase + SZ_PART;
    const uint32_t swz = (uint32_t)(ln << 4);

#pragma unroll
    for (int ks = 0; ks < NK16; ks++) {
        const uint32_t xh = (uint32_t)((ks * 2 + (u & 1)) << 4) ^ swz;
        uint32_t bf[14];
        // --- wh part ---
        ldsm4(bf + 0, hibase + (uint32_t)((0 * 16 + nb) * 128) + xh);
        ldsm4(bf + 4, hibase + (uint32_t)((1 * 16 + nb) * 128) + xh);
        ldsm4(bf + 8, hibase + (uint32_t)((2 * 16 + nb) * 128) + xh);
        ldsm2(bf + 12, hibase + (uint32_t)((48 + ln) * 128) + xh);
#pragma unroll
        for (int tt = 0; tt < 2; tt++)
#pragma unroll
            for (int nt = 0; nt < 7; nt++) mma_f16(C[tt][nt], Ah[tt][ks], bf[2*nt], bf[2*nt+1]);
        // --- wl part (same A fragments) ---
        ldsm4(bf + 0, lobase + (uint32_t)((0 * 16 + nb) * 128) + xh);
        ldsm4(bf + 4, lobase + (uint32_t)((1 * 16 + nb) * 128) + xh);
        ldsm4(bf + 8, lobase + (uint32_t)((2 * 16 + nb) * 128) + xh);
        ldsm2(bf + 12, lobase + (uint32_t)((48 + ln) * 128) + xh);
#pragma unroll
        for (int tt = 0; tt < 2; tt++)
#pragma unroll
            for (int nt = 0; nt < 7; nt++) mma_f16(C[tt][nt], Ah[tt][ks], bf[2*nt], bf[2*nt+1]);
    }

    if (TAIL) {
        // single merged k8 step (chunk 6 of wh part holds the mixed tail)
        const uint32_t x8 = (uint32_t)(96u ^ (uint32_t)(ln << 4));
        uint32_t b8[8];
        ldsm4(b8 + 0, hibase + (uint32_t)(lane * 128) + x8);
        ldsm4(b8 + 4, hibase + (uint32_t)((32 + lane) * 128) + x8);
#pragma unroll
        for (int tt = 0; tt < 2; tt++)
#pragma unroll
            for (int nt = 0; nt < 7; nt++) mma_f16_8(C[tt][nt], at0[tt], at1[tt], b8[nt]);
    }
}

// ReLU + convert C (7 n-tiles) into next layer's fp16 A fragments (3 k16 + tail pair)
__device__ __forceinline__ void epilogue(float C[7][4], uint32_t Ah[3][4], uint32_t* Ah3) {
#pragma unroll
    for (int nt = 0; nt < 7; nt++)
#pragma unroll
        for (int q = 0; q < 4; q++) C[nt][q] = fmaxf(C[nt][q], 0.f);
#pragma unroll
    for (int s = 0; s < 3; s++) {
        Ah[s][0] = pack_h2(C[2*s][0],   C[2*s][1]);
        Ah[s][1] = pack_h2(C[2*s][2],   C[2*s][3]);
        Ah[s][2] = pack_h2(C[2*s+1][0], C[2*s+1][1]);
        Ah[s][3] = pack_h2(C[2*s+1][2], C[2*s+1][3]);
    }
    Ah3[0] = pack_h2(C[6][0], C[6][1]);
    Ah3[1] = pack_h2(C[6][2], C[6][3]);
}

// build layer-0 A fragments for one tile from x (round to fp16)
__device__ __forceinline__ void build_a0(const float* x, int n, int base, int g, int t2,
                                         uint32_t Ah[3][4]) {
    int r0 = base + g;     if (r0 > n - 1) r0 = n - 1;
    int r1 = base + g + 8; if (r1 > n - 1) r1 = n - 1;
    const float2* p0 = (const float2*)(x + (size_t)r0 * IN_DIM + t2);
    const float2* p1 = (const float2*)(x + (size_t)r1 * IN_DIM + t2);
    float2 v00 = p0[0], v01 = p0[4];
    float2 v10 = p1[0], v11 = p1[4];
    Ah[0][0] = pack_h2(v00.x, v00.y);
    Ah[0][1] = pack_h2(v10.x, v10.y);
    Ah[0][2] = pack_h2(v01.x, v01.y);
    Ah[0][3] = pack_h2(v11.x, v11.y);
}

__global__ __launch_bounds__(THREADS, 1)
void mlp_mma_kernel(const float* __restrict__ x,
                    const float* __restrict__ W0, const float* __restrict__ b0,
                    const float* __restrict__ Wh, const float* __restrict__ bh,
                    const float* __restrict__ Wo, const float* __restrict__ bo,
                    float* __restrict__ out, int n, int npairs, int nwarps) {
    extern __shared__ char sm[];
    const uint32_t sb = smem_u32(sm);
    const int tid  = threadIdx.x;
    const int wid  = tid >> 5;
    const int lane = tid & 31;

    // ---- stage weights: wh/wl fp16, zero-padded, swizzled; merged tail in wh chunk 6 ----
    for (int idx = tid; idx < NL * 56 * 64; idx += THREADS) {
        int l = idx / 3584;
        int r = idx - l * 3584;
        int nrow = r >> 6, k = r & 63;
        int Kreal = (l == 0) ? IN_DIM : WIDTH;
        __half hv, lv;
        if (k < 48) {
            float f = 0.f;
            if (nrow < WIDTH && k < Kreal)
                f = (l == 0) ? W0[nrow * IN_DIM + k] : Wh[((l - 1) * WIDTH + nrow) * WIDTH + k];
            hv = __float2half_rn(f);
            lv = __float2half_rn(f - __half2float(hv));
        } else {
            int m = k - 48, p = m >> 1, c = m & 1;
            int kk = 48 + c;
            float f = 0.f;
            if (l > 0 && nrow < WIDTH && kk < Kreal)
                f = Wh[((l - 1) * WIDTH + nrow) * WIDTH + kk];
            __half fh = __float2half_rn(f);
            __half fl = __float2half_rn(f - __half2float(fh));
            hv = (p == 0) ? fh : (p == 1 ? fl : __float2half_rn(0.f));
            lv = __float2half_rn(0.f);
        }
        uint32_t so = swoff(nrow, k);
        *(__half*)(sm + OFF_WH + l * SZ_LAYER + so)           = hv;
        *(__half*)(sm + OFF_WH + l * SZ_LAYER + SZ_PART + so) = lv;
    }
    for (int idx = tid; idx < 8 * 64; idx += THREADS) {
        int nrow = idx >> 6, k = idx & 63;
        __half hv, lv;
        if (k < 48) {
            float f = (nrow < OUT_DIM) ? Wo[nrow * WIDTH + k] : 0.f;
            hv = __float2half_rn(f);
            lv = __float2half_rn(f - __half2float(hv));
        } else {
            int m = k - 48, p = m >> 1, c = m & 1;
            int kk = 48 + c;
            float f = (nrow < OUT_DIM && kk < WIDTH) ? Wo[nrow * WIDTH + kk] : 0.f;
            __half fh = __float2half_rn(f);
            __half fl = __float2half_rn(f - __half2float(fh));
            hv = (p == 0) ? fh : (p == 1 ? fl : __float2half_rn(0.f));
            lv = __float2half_rn(0.f);
        }
        uint32_t so = swoff(nrow, k);
        *(__half*)(sm + OFF_WO + so)        = hv;
        *(__half*)(sm + OFF_WO + 1024 + so) = lv;
    }
    for (int idx = tid; idx < NL * 56; idx += THREADS) {
        int l = idx / 56, j = idx - l * 56;
        float f = 0.f;
        if (j < WIDTH) f = (l == 0) ? b0[j] : bh[(l - 1) * WIDTH + j];
        *(float*)(sm + OFF_BIAS + idx * 4) = f;
    }
    if (tid < 8) *(float*)(sm + OFF_BO + tid * 4) = (tid < OUT_DIM) ? bo[tid] : 0.f;
    __syncthreads();

    const int g  = lane >> 2;
    const int t2 = (lane & 3) * 2;
    const int ln = lane & 7;
    const int u  = lane >> 3;

    for (int tp = blockIdx.x * WARPS + wid; tp < npairs; tp += nwarps) {
        const int base0 = tp << 5;
        const int base1 = base0 + 16;
        uint32_t Ah[2][3][4], Ah3[2][2];
        uint32_t at0[2], at1[2];
        float C[2][7][4];

        // ---- build layer-0 A fragments from x (K=16 exact, 1 k-step) ----
        build_a0(x, n, base0, g, t2, Ah[0]);
        build_a0(x, n, base1, g, t2, Ah[1]);
        at0[0] = at0[1] = at1[0] = at1[1] = 0u;
        layer_mma2<1, false>(sm, sb, 0, Ah, at0, at1, C, lane);

        // ---- 14 hidden layers (K = 50: 3x k16 x 2 parts + 1 merged k8 tail) ----
#pragma unroll 1
        for (int l = 1; l < NL; l++) {
            epilogue(C[0], Ah[0], Ah3[0]);
            epilogue(C[1], Ah[1], Ah3[1]);
            make_tail(Ah3[0], lane, at0[0], at1[0]);
            make_tail(Ah3[1], lane, at0[1], at1[1]);
            layer_mma2<3, true>(sm, sb, l, Ah, at0, at1, C, lane);
        }

        // ---- output layer: 50 -> 4 (single n-tile, shared weight frags) ----
        epilogue(C[0], Ah[0], Ah3[0]);
        epilogue(C[1], Ah[1], Ah3[1]);
        make_tail(Ah3[0], lane, at0[0], at1[0]);
        make_tail(Ah3[1], lane, at0[1], at1[1]);
        {
            float Co[2][4];
            float2 bv = *(const float2*)(sm + OFF_BO + t2 * 4);
#pragma unroll
            for (int tt = 0; tt < 2; tt++) {
                Co[tt][0] = bv.x; Co[tt][1] = bv.y; Co[tt][2] = bv.x; Co[tt][3] = bv.y;
            }
            const uint32_t hibase = sb + OFF_WO;
            const uint32_t lobase = hibase + 1024;
#pragma unroll
            for (int ks = 0; ks < 3; ks++) {
                const uint32_t xh = (uint32_t)((ks * 2 + (u & 1)) << 4) ^ (uint32_t)(ln << 4);
                uint32_t w[2];
                ldsm2(w, hibase + (uint32_t)(ln * 128) + xh);
                mma_f16(Co[0], Ah[0][ks], w[0], w[1]);
                mma_f16(Co[1], Ah[1][ks], w[0], w[1]);
                ldsm2(w, lobase + (uint32_t)(ln * 128) + xh);
                mma_f16(Co[0], Ah[0][ks], w[0], w[1]);
                mma_f16(Co[1], Ah[1][ks], w[0], w[1]);
            }
            {
                const uint32_t x8 = (uint32_t)(96u ^ (uint32_t)(ln << 4));
                uint32_t w0;
                ldsm1(w0, hibase + (uint32_t)(ln * 128) + x8);
                mma_f16_8(Co[0], at0[0], at1[0], w0);
                mma_f16_8(Co[1], at0[1], at1[1], w0);
            }
            if (t2 < OUT_DIM) {
#pragma unroll
                for (int tt = 0; tt < 2; tt++) {
                    int base = tt ? base1 : base0;
                    int r0 = base + g, r1 = base + g + 8;
                    if (r0 < n) *(float2*)(out + (size_t)r0 * OUT_DIM + t2) = make_float2(Co[tt][0], Co[tt][1]);
                    if (r1 < n) *(float2*)(out + (size_t)r1 * OUT_DIM + t2) = make_float2(Co[tt][2], Co[tt][3]);
                }
            }
        }
    }
}

extern "C" void kernel_launch(void* const* d_in, const int* in_sizes, int n_in,
                              void* d_out, int out_size) {
    const float* x  = (const float*)d_in[0];
    const float* W0 = (const float*)d_in[1];
    const float* b0 = (const float*)d_in[2];
    const float* Wh = (const float*)d_in[3];
    const float* bh = (const float*)d_in[4];
    const float* Wo = (const float*)d_in[5];
    const float* bo = (const float*)d_in[6];
    float* out = (float*)d_out;

    int n = in_sizes[0] / IN_DIM;
    int npairs = (n + 31) >> 5;

    int sms = 148;
    cudaDeviceGetAttribute(&sms, cudaDevAttrMultiProcessorCount, 0);

    cudaFuncSetAttribute(mlp_mma_kernel, cudaFuncAttributeMaxDynamicSharedMemorySize,
                         SMEM_BYTES);

    int nwarps = sms * WARPS;
    mlp_mma_kernel<<<sms, THREADS, SMEM_BYTES>>>(x, W0, b0, Wh, bh, Wo, bo, out,
                                                 n, npairs, nwarps);
}

// round 12
// speedup vs baseline: 1.4344x; 1.4344x over previous
#include <cuda_runtime.h>
#include <cstdint>

#define IN_DIM   16
#define WIDTH    50
#define OUT_DIM  4
#define NL       15            // layer0 (16->50) + 14 hidden (50->50)
#define THREADS  384
#define WARPS    (THREADS/32)

// Weight layout: per (layer, ks): 16 matrices of 128B (nt 0..7 x b 0..1),
// matrix (nt,b) at (nt>>1)*512 + ((nt&1)*2+b)*128. Matrix row j (16B) =
// { W[n=nt*8+j][kinv(8ks+4b+0..3)] } as tf32-rounded fp32.
#define SZ_LAYER  14336                   // 7 ks * 2048
#define OFF_WH    0                       // 15 * 14336 = 215040
#define OFF_WO    (NL*SZ_LAYER)           // 215040: 8 ks * 2 * 128 = 2048
#define OFF_BIAS  (OFF_WO + 2048)         // 217088: [15][56] f32
#define OFF_BO    (OFF_BIAS + NL*56*4)    // 220448: [8] f32
#define SMEM_BYTES (OFF_BO + 32)          // 220480

__device__ __forceinline__ uint32_t smem_u32(const void* p) {
    uint32_t a;
    asm("{ .reg .u64 t; cvta.to.shared.u64 t, %1; cvt.u32.u64 %0, t; }" : "=r"(a) : "l"(p));
    return a;
}
__device__ __forceinline__ void ldsm4(uint32_t* r, uint32_t a) {
    asm volatile("ldmatrix.sync.aligned.m8n8.x4.shared.b16 {%0,%1,%2,%3}, [%4];"
                 : "=r"(r[0]), "=r"(r[1]), "=r"(r[2]), "=r"(r[3]) : "r"(a));
}
// tf32 MMA; A passed in prev-C register order {c0,c2,c1,c3} -> {a0,a1,a2,a3}
__device__ __forceinline__ void mma_tf32(float* c, const float* a, uint32_t b0, uint32_t b1) {
    asm("mma.sync.aligned.m16n8k8.row.col.f32.tf32.tf32.f32 "
        "{%0,%1,%2,%3}, {%4,%5,%6,%7}, {%8,%9}, {%0,%1,%2,%3};"
        : "+f"(c[0]), "+f"(c[1]), "+f"(c[2]), "+f"(c[3])
        : "r"(__float_as_uint(a[0])), "r"(__float_as_uint(a[2])),
          "r"(__float_as_uint(a[1])), "r"(__float_as_uint(a[3])),
          "r"(b0), "r"(b1));
}
__device__ __forceinline__ float to_tf32(float v) {
    uint32_t u;
    asm("cvt.rna.tf32.f32 %0, %1;" : "=r"(u) : "f"(v));
    return __uint_as_float(u);
}
__device__ __forceinline__ float relu_tf32(float v) {
    return to_tf32(fmaxf(v, 0.f));
}
// kinv: neuron index feeding MMA k-slot ks (within-8-group bit permutation)
__device__ __forceinline__ int kinv(int kslot) {
    return (kslot & ~7) | ((kslot & 3) << 1) | ((kslot >> 2) & 1);
}

// Dual-tile tf32 layer: C[2][7][4] = bias + A * W^T, NKS k8-steps.
template <int NKS>
__device__ __forceinline__ void layer_mma2(const char* sm, uint32_t sb, int layer,
                                           const float (&A)[2][NKS][4],
                                           float (&C)[2][7][4],
                                           int lane, uint32_t laneoff) {
    const int t = lane & 3;
    const float* bias = (const float*)(sm + OFF_BIAS + layer * 224);
#pragma unroll
    for (int nt = 0; nt < 7; nt++) {
        float2 bv = *(const float2*)(bias + nt * 8 + 2 * t);
#pragma unroll
        for (int tt = 0; tt < 2; tt++) {
            C[tt][nt][0] = bv.x; C[tt][nt][1] = bv.y;
            C[tt][nt][2] = bv.x; C[tt][nt][3] = bv.y;
        }
    }
    const uint32_t base = sb + OFF_WH + (uint32_t)layer * SZ_LAYER + laneoff;
#pragma unroll
    for (int ks = 0; ks < NKS; ks++) {
        const uint32_t kb = base + (uint32_t)ks * 2048;
        uint32_t bf[16];
        ldsm4(bf + 0,  kb);
        ldsm4(bf + 4,  kb + 512);
        ldsm4(bf + 8,  kb + 1024);
        ldsm4(bf + 12, kb + 1536);
#pragma unroll
        for (int tt = 0; tt < 2; tt++)
#pragma unroll
            for (int nt = 0; nt < 7; nt++)
                mma_tf32(C[tt][nt], A[tt][ks], bf[2 * nt], bf[2 * nt + 1]);
    }
}

// ReLU + tf32-round all 28 accumulators of both tiles (in place)
__device__ __forceinline__ void relu_cvt(float (&P)[2][7][4]) {
#pragma unroll
    for (int tt = 0; tt < 2; tt++)
#pragma unroll
        for (int nt = 0; nt < 7; nt++)
#pragma unroll
            for (int q = 0; q < 4; q++)
                P[tt][nt][q] = relu_tf32(P[tt][nt][q]);
}

__global__ __launch_bounds__(THREADS, 1)
void mlp_mma_kernel(const float* __restrict__ x,
                    const float* __restrict__ W0, const float* __restrict__ b0,
                    const float* __restrict__ Wh, const float* __restrict__ bh,
                    const float* __restrict__ Wo, const float* __restrict__ bo,
                    float* __restrict__ out, int n, int npairs, int nwarps) {
    extern __shared__ char sm[];
    const uint32_t sb = smem_u32(sm);
    const int tid  = threadIdx.x;
    const int wid  = tid >> 5;
    const int lane = tid & 31;

    // ---- stage hidden+first-layer weights (tf32, kinv-permuted, ldsm-transposed) ----
    for (int idx = tid; idx < NL * 3584; idx += THREADS) {
        int l  = idx / 3584;
        int f  = idx - l * 3584;
        int ks = f >> 9;
        int mat = (f >> 5) & 15;
        int w  = f & 31;
        int j  = w >> 2, tp = w & 3;
        int nt = ((mat >> 2) << 1) | ((mat >> 1) & 1);
        int b  = mat & 1;
        int nn = nt * 8 + j;
        int kslot = ks * 8 + b * 4 + tp;
        int c, Kr;
        if (l == 0) { c = kslot; Kr = IN_DIM; }
        else        { c = kinv(kslot); Kr = WIDTH; }
        float v = 0.f;
        if (nn < WIDTH && c < Kr)
            v = (l == 0) ? W0[nn * IN_DIM + c] : Wh[((l - 1) * WIDTH + nn) * WIDTH + c];
        *(float*)(sm + OFF_WH + l * SZ_LAYER + ks * 2048 + mat * 128 + j * 16 + tp * 4) = to_tf32(v);
    }
    // ---- output weights: [ks 0..7][b][128B] ----
    for (int idx = tid; idx < 512; idx += THREADS) {
        int ks = idx >> 6;
        int b  = (idx >> 5) & 1;
        int w  = idx & 31;
        int j  = w >> 2, tp = w & 3;
        int kslot = ks * 8 + b * 4 + tp;
        int c = kinv(kslot);
        float v = (j < OUT_DIM && c < WIDTH) ? Wo[j * WIDTH + c] : 0.f;
        *(float*)(sm + OFF_WO + ks * 256 + b * 128 + j * 16 + tp * 4) = to_tf32(v);
    }
    for (int idx = tid; idx < NL * 56; idx += THREADS) {
        int l = idx / 56, j = idx - l * 56;
        float f = 0.f;
        if (j < WIDTH) f = (l == 0) ? b0[j] : bh[(l - 1) * WIDTH + j];
        *(float*)(sm + OFF_BIAS + idx * 4) = f;
    }
    if (tid < 8) *(float*)(sm + OFF_BO + tid * 4) = (tid < OUT_DIM) ? bo[tid] : 0.f;
    __syncthreads();

    const int g = lane >> 2;
    const int t = lane & 3;
    const uint32_t laneoff = (uint32_t)(((lane >> 3) << 7) + ((lane & 7) << 4));

    for (int tp = blockIdx.x * WARPS + wid; tp < npairs; tp += nwarps) {
        const int base0 = tp << 5;
        float P0[2][7][4], P1[2][7][4];

        // ---- layer 0: A from x (K=16 -> 2 k8 steps), C -> P0 ----
        {
            float xa[2][2][4];
#pragma unroll
            for (int tt = 0; tt < 2; tt++) {
                int bb = base0 + tt * 16;
                int r0 = bb + g;     if (r0 > n - 1) r0 = n - 1;
                int r1 = bb + g + 8; if (r1 > n - 1) r1 = n - 1;
                const float* p0 = x + (size_t)r0 * IN_DIM;
                const float* p1 = x + (size_t)r1 * IN_DIM;
#pragma unroll
                for (int s = 0; s < 2; s++) {
                    xa[tt][s][0] = to_tf32(p0[8 * s + t]);         // a0 (g,   k=8s+t)
                    xa[tt][s][2] = to_tf32(p1[8 * s + t]);         // a1 (g+8, k=8s+t)
                    xa[tt][s][1] = to_tf32(p0[8 * s + 4 + t]);     // a2 (g,   k=8s+4+t)
                    xa[tt][s][3] = to_tf32(p1[8 * s + 4 + t]);     // a3 (g+8, k=8s+4+t)
                }
            }
            layer_mma2<2>(sm, sb, 0, xa, P0, lane, laneoff);
            relu_cvt(P0);
        }

        // ---- 14 hidden layers, ping-pong P0 <-> P1 ----
#pragma unroll 1
        for (int l = 1; l < NL; l += 2) {
            layer_mma2<7>(sm, sb, l, P0, P1, lane, laneoff);
            relu_cvt(P1);
            layer_mma2<7>(sm, sb, l + 1, P1, P0, lane, laneoff);
            relu_cvt(P0);
        }

        // ---- output layer: 50 -> 4 ----
        {
            uint32_t wb[16];
#pragma unroll
            for (int p = 0; p < 4; p++)
                ldsm4(wb + 4 * p, sb + OFF_WO + (uint32_t)p * 512 + laneoff);

            float Co[2][4];
            float2 bv = *(const float2*)(sm + OFF_BO + 2 * t * 4);
#pragma unroll
            for (int tt = 0; tt < 2; tt++) {
                Co[tt][0] = bv.x; Co[tt][1] = bv.y; Co[tt][2] = bv.x; Co[tt][3] = bv.y;
            }
#pragma unroll
            for (int ks = 0; ks < 7; ks++)
#pragma unroll
                for (int tt = 0; tt < 2; tt++)
                    mma_tf32(Co[tt], P0[tt][ks], wb[2 * ks], wb[2 * ks + 1]);

            if (t < 2) {
#pragma unroll
                for (int tt = 0; tt < 2; tt++) {
                    int bb = base0 + tt * 16;
                    int r0 = bb + g, r1 = bb + g + 8;
                    if (r0 < n) *(float2*)(out + (size_t)r0 * OUT_DIM + 2 * t) = make_float2(Co[tt][0], Co[tt][1]);
                    if (r1 < n) *(float2*)(out + (size_t)r1 * OUT_DIM + 2 * t) = make_float2(Co[tt][2], Co[tt][3]);
                }
            }
        }
    }
}

extern "C" void kernel_launch(void* const* d_in, const int* in_sizes, int n_in,
                              void* d_out, int out_size) {
    const float* x  = (const float*)d_in[0];
    const float* W0 = (const float*)d_in[1];
    const float* b0 = (const float*)d_in[2];
    const float* Wh = (const float*)d_in[3];
    const float* bh = (const float*)d_in[4];
    const float* Wo = (const float*)d_in[5];
    const float* bo = (const float*)d_in[6];
    float* out = (float*)d_out;

    int n = in_sizes[0] / IN_DIM;
    int npairs = (n + 31) >> 5;

    int sms = 148;
    cudaDeviceGetAttribute(&sms, cudaDevAttrMultiProcessorCount, 0);

    cudaFuncSetAttribute(mlp_mma_kernel, cudaFuncAttributeMaxDynamicSharedMemorySize,
                         SMEM_BYTES);

    int nwarps = sms * WARPS;
    mlp_mma_kernel<<<sms, THREADS, SMEM_BYTES>>>(x, W0, b0, Wh, bh, Wo, bo, out,
                                                 n, npairs, nwarps);
}